// round 14
// baseline (speedup 1.0000x reference)
#include <cuda_runtime.h>
#include <cuda_bf16.h>
#include <cuda_fp16.h>
#include <math.h>
#include <stdint.h>

// Problem constants
#define B_ 8
#define C_ 256
#define N_ 4096
#define H_ 8
#define D_ 32
#define P_ 64

// Scratch (device globals; allocation-free contract)
// g_proj layout: [slab][b][row256][n] (fp16), slab: 0=q_sa,1=k_sa,2=v_sa,3=q_c,4=k_c,5=v_c
__device__ __half g_proj[6u * 8u * 256u * 4096u];     // 100 MB
__device__ float g_sumsq[3 * 2048];                   // row sum-of-squares (atomic)
__device__ float g_kvp[8][2 * 64 * 32 * 64];          // K-split partials [sp][row*64+p]
__device__ float g_kv[2 * 64 * 32 * 64];
__device__ float g_gram[64 * 32 * 32];                // channel gram partial sums (atomic)
__device__ float g_attn[64 * 32 * 32];
__device__ __half g_xsa[8u * 8u * 32u * 4096u];       // spatial out [b][h][d][n], fp16

// fp16 operands for the tensor-core GEMMs
__device__ __half g_Wh[1536 * 256];
__device__ __half g_xh[8u * 4096u * 256u];            // [b][n][c]  (transposed)
__device__ __half g_EFh[64 * 4096];                   // EF transposed: [p][n]

// ---------------------------------------------------------------------------
// helpers
// ---------------------------------------------------------------------------
__device__ __forceinline__ uint32_t smem_u32(const void* p) {
    uint32_t a;
    asm("{ .reg .u64 t; cvta.to.shared.u64 t, %1; cvt.u32.u64 %0, t; }" : "=r"(a) : "l"(p));
    return a;
}
#define CP_ASYNC16(dst, src) \
    asm volatile("cp.async.cg.shared.global [%0], [%1], 16;" :: "r"(dst), "l"(src))
#define CP_COMMIT() asm volatile("cp.async.commit_group;" ::: "memory")
#define CP_WAITG1() asm volatile("cp.async.wait_group 1;" ::: "memory")

__device__ __forceinline__ void mma_f16(float* d, const uint32_t* a, const uint32_t* bb) {
    asm volatile(
        "mma.sync.aligned.m16n8k16.row.col.f32.f16.f16.f32 "
        "{%0,%1,%2,%3}, {%4,%5,%6,%7}, {%8,%9}, {%0,%1,%2,%3};"
        : "+f"(d[0]), "+f"(d[1]), "+f"(d[2]), "+f"(d[3])
        : "r"(a[0]), "r"(a[1]), "r"(a[2]), "r"(a[3]), "r"(bb[0]), "r"(bb[1]));
}
__device__ __forceinline__ void ldsm_x4(uint32_t& r0, uint32_t& r1, uint32_t& r2,
                                        uint32_t& r3, uint32_t addr) {
    asm volatile("ldmatrix.sync.aligned.m8n8.x4.shared.b16 {%0,%1,%2,%3}, [%4];"
                 : "=r"(r0), "=r"(r1), "=r"(r2), "=r"(r3) : "r"(addr));
}
__device__ __forceinline__ void ldsm_x4t(uint32_t& r0, uint32_t& r1, uint32_t& r2,
                                         uint32_t& r3, uint32_t addr) {
    asm volatile("ldmatrix.sync.aligned.m8n8.x4.trans.shared.b16 {%0,%1,%2,%3}, [%4];"
                 : "=r"(r0), "=r"(r1), "=r"(r2), "=r"(r3) : "r"(addr));
}

// FFMA-only exp (avoids MUFU pipe), ~2e-6 relative accuracy.
__device__ __forceinline__ float fexp(float x) {
    const float L2E = 1.4426950408889634f;
    float t = fmaf(x, L2E, 12582912.0f);
    float n = t - 12582912.0f;
    float f = fmaf(x, L2E, -n);
    float p = 1.33978035e-3f;
    p = fmaf(p, f, 9.67770915e-3f);
    p = fmaf(p, f, 5.55041086e-2f);
    p = fmaf(p, f, 2.40226507e-1f);
    p = fmaf(p, f, 6.93147182e-1f);
    p = fmaf(p, f, 1.0f);
    int e = __float2int_rn(n);
    if (e < -126) e = -126;
    if (e > 126) e = 126;
    return __int_as_float((e + 127) << 23) * p;
}

__device__ __forceinline__ float inv_norm(float ss) {
    return 1.f / fmaxf(sqrtf(ss), 1e-12f);
}

// ---------------------------------------------------------------------------
// K0w: pack weights into fp16 (GEMM row order) + zero accumulators.
// ---------------------------------------------------------------------------
__global__ __launch_bounds__(256) void k0w_pack(const float* __restrict__ Wsa,
                                                const float* __restrict__ Wsc) {
    int e = blockIdx.x * 256 + threadIdx.x;       // 0 .. 393215
    if (e < 3 * 2048) g_sumsq[e] = 0.f;
    if (e < 64 * 32 * 32) g_gram[e] = 0.f;
    int r = e >> 8, c = e & 255;
    int p = (r >= 768) ? 1 : 0;
    int rr = r - p * 768;
    int t = rr >> 8;
    const float* Wp = p ? Wsc : Wsa;
    int srow = rr + ((p == 0 && t == 2) ? 256 : 0);
    g_Wh[e] = __float2half(Wp[(size_t)srow * 256 + c]);
}

// ---------------------------------------------------------------------------
// K0x: transpose x [b][c][n] -> [b][n][c], fp16.
// ---------------------------------------------------------------------------
__global__ __launch_bounds__(128) void k0x_pack(const float* __restrict__ x) {
    int n0 = blockIdx.x * 128;
    int b = blockIdx.y;
    __shared__ float sm[64][132];
    int tid = threadIdx.x;
    const float* xb = x + (size_t)b * C_ * N_;

    for (int c0 = 0; c0 < 256; c0 += 64) {
#pragma unroll
        for (int i = 0; i < 16; i++) {
            int u = tid + i * 128;
            int c = u >> 5, nq = u & 31;
            *(float4*)&sm[c][nq * 4] =
                *(const float4*)(xb + (size_t)(c0 + c) * N_ + n0 + nq * 4);
        }
        __syncthreads();
        uint32_t buf[32];
#pragma unroll
        for (int c = 0; c < 64; c += 2) {
            __half2 hv = __floats2half2_rn(sm[c][tid], sm[c + 1][tid]);
            buf[c >> 1] = *(uint32_t*)&hv;
        }
        size_t obase = ((size_t)b * 4096 + n0 + tid) * 256 + c0;
#pragma unroll
        for (int j = 0; j < 8; j++)
            *(uint4*)&g_xh[obase + j * 8] = *(uint4*)&buf[j * 4];
        __syncthreads();
    }
}

// ---------------------------------------------------------------------------
// K0e: transpose EF [n][p] fp32 -> g_EFh [p][n] fp16.
// ---------------------------------------------------------------------------
__global__ __launch_bounds__(256) void k0e_pack(const float* __restrict__ EF) {
    __shared__ float tile[64][65];
    int n0 = blockIdx.x * 64;
    int tid = threadIdx.x;
#pragma unroll
    for (int i = 0; i < 16; i++) {
        int u = tid + i * 256;
        int r = u >> 6, c = u & 63;
        tile[c][r] = EF[(size_t)(n0 + r) * 64 + c];
    }
    __syncthreads();
#pragma unroll
    for (int i = 0; i < 16; i++) {
        int u = tid + i * 256;
        int p = u >> 6, j = u & 63;
        g_EFh[(size_t)p * 4096 + n0 + j] = __float2half(tile[p][j]);
    }
}

// ---------------------------------------------------------------------------
// K1: fp16 mma.sync GEMM, fully unrolled 3-stage pipeline, x4-paired B loads.
// CTA 128m x 128n; 8 warps (2m x 4n); 8 k32 steps.
// ---------------------------------------------------------------------------
#define K1_TSTRIDE 40
#define K1_TILE_HALVES (128 * K1_TSTRIDE)

__global__ __launch_bounds__(256) void k1_mma() {
    extern __shared__ __half sm1[];
    const int n0 = blockIdx.x * 128;
    const int my = blockIdx.y;                  // 0..11
    const int b  = blockIdx.z;
    const int m0 = my * 128;

    const int tid = threadIdx.x;
    const int wid = tid >> 5, lane = tid & 31;
    const int wm = (wid & 1) * 64, wn = (wid >> 1) * 32;
    const int g = lane >> 2, t4 = lane & 3;

    // unified x4 lane->addr pattern: row = lane&15, col-seg = (lane>>4)*8
    const int x4_row = lane & 15, x4_col = (lane >> 4) * 8;

#define TILE(buf, t) (sm1 + ((buf) * 2 + (t)) * K1_TILE_HALVES)

    float acc[4][4][4];
#pragma unroll
    for (int mt = 0; mt < 4; mt++)
#pragma unroll
        for (int nt = 0; nt < 4; nt++)
#pragma unroll
            for (int j = 0; j < 4; j++) acc[mt][nt][j] = 0.f;

    const int lr0 = tid >> 2;
    const int ls0 = (tid & 3) * 8;

#define LOAD_STEP(kc, buf)                                                              \
    do {                                                                                \
        int _k0 = (kc) * 32;                                                            \
        const __half* _A = g_Wh + (size_t)m0 * 256 + _k0;                               \
        const __half* _B = g_xh + ((size_t)b * 4096 + n0) * 256 + _k0;                  \
        CP_ASYNC16(smem_u32(TILE(buf,0) + lr0 * K1_TSTRIDE + ls0), _A + (size_t)lr0 * 256 + ls0); \
        CP_ASYNC16(smem_u32(TILE(buf,0) + (lr0+64) * K1_TSTRIDE + ls0), _A + (size_t)(lr0+64) * 256 + ls0); \
        CP_ASYNC16(smem_u32(TILE(buf,1) + lr0 * K1_TSTRIDE + ls0), _B + (size_t)lr0 * 256 + ls0); \
        CP_ASYNC16(smem_u32(TILE(buf,1) + (lr0+64) * K1_TSTRIDE + ls0), _B + (size_t)(lr0+64) * 256 + ls0); \
    } while (0)

    LOAD_STEP(0, 0); CP_COMMIT();
    LOAD_STEP(1, 1); CP_COMMIT();

#pragma unroll
    for (int s = 0; s < 8; s++) {
        const int buf = s % 3;
        CP_WAITG1();
        __syncthreads();

        if (s + 2 < 8) LOAD_STEP(s + 2, (s + 2) % 3);
        CP_COMMIT();

#pragma unroll
        for (int h = 0; h < 2; h++) {
            uint32_t af[4][4], bfr[4][2];
            const __half* Abase = TILE(buf, 0) + (size_t)x4_row * K1_TSTRIDE + h * 16 + x4_col;
            const __half* Bbase = TILE(buf, 1) + (size_t)x4_row * K1_TSTRIDE + h * 16 + x4_col;
#pragma unroll
            for (int mt = 0; mt < 4; mt++)
                ldsm_x4(af[mt][0], af[mt][1], af[mt][2], af[mt][3],
                        smem_u32(Abase + (wm + mt * 16) * K1_TSTRIDE));
#pragma unroll
            for (int pr = 0; pr < 2; pr++)
                ldsm_x4(bfr[2 * pr][0], bfr[2 * pr + 1][0],
                        bfr[2 * pr][1], bfr[2 * pr + 1][1],
                        smem_u32(Bbase + (wn + pr * 16) * K1_TSTRIDE));
#pragma unroll
            for (int mt = 0; mt < 4; mt++)
#pragma unroll
                for (int nt = 0; nt < 4; nt++)
                    mma_f16(acc[mt][nt], af[mt], bfr[nt]);
        }
    }
#undef LOAD_STEP
#undef TILE

    // epilogue -> g_proj (fp16) + fused sumsq for slabs 0,3,4
    const int slab = my >> 1;
    const int rb = (my & 1) * 128;
    const int which = (slab == 0) ? 0 : (slab == 3 ? 1 : (slab == 4 ? 2 : -1));
#pragma unroll
    for (int mt = 0; mt < 4; mt++) {
        int r0 = rb + wm + mt * 16 + g;
        __half* p0 = g_proj + (((size_t)slab * 8 + b) * 256 + r0) * (size_t)N_ + n0 + wn;
        __half* p1 = p0 + 8 * (size_t)N_;
        float ss0 = 0.f, ss1 = 0.f;
#pragma unroll
        for (int nt = 0; nt < 4; nt++) {
            float a0 = acc[mt][nt][0], a1 = acc[mt][nt][1];
            float a2 = acc[mt][nt][2], a3 = acc[mt][nt][3];
            *(__half2*)(p0 + nt * 8 + 2 * t4) = __floats2half2_rn(a0, a1);
            *(__half2*)(p1 + nt * 8 + 2 * t4) = __floats2half2_rn(a2, a3);
            ss0 += a0 * a0 + a1 * a1;
            ss1 += a2 * a2 + a3 * a3;
        }
        if (which >= 0) {
            ss0 += __shfl_xor_sync(0xffffffffu, ss0, 1);
            ss0 += __shfl_xor_sync(0xffffffffu, ss0, 2);
            ss1 += __shfl_xor_sync(0xffffffffu, ss1, 1);
            ss1 += __shfl_xor_sync(0xffffffffu, ss1, 2);
            if (t4 == 0) {
                int row = b * 256 + r0;
                atomicAdd(&g_sumsq[which * 2048 + row], ss0);
                atomicAdd(&g_sumsq[which * 2048 + row + 8], ss1);
            }
        }
    }
}

// ---------------------------------------------------------------------------
// K3: Linformer projection GEMM, fully unrolled, x4-paired B loads.
// CTA 128m x 64n; 8 warps (4m x 2n); 16 k32 steps; K-split 8.
// ---------------------------------------------------------------------------
#define K3_STRIDE 40
__global__ __launch_bounds__(256) void k3_mma() {
    __shared__ __half As[3][128][K3_STRIDE];
    __shared__ __half Bs[3][64][K3_STRIDE];
    const int m0 = blockIdx.x * 128;
    const int sp = blockIdx.y;
    const int kb = sp * 512;

    const int tid = threadIdx.x;
    const int wid = tid >> 5, lane = tid & 31;
    const int wm = (wid >> 1) * 32;
    const int wn = (wid & 1) * 32;
    const int g = lane >> 2, t4 = lane & 3;

    const int x4_row = lane & 15, x4_col = (lane >> 4) * 8;

    const __half* Ag = g_proj + (size_t)2048 * N_;

    float acc[2][4][4];
#pragma unroll
    for (int mt = 0; mt < 2; mt++)
#pragma unroll
        for (int nt = 0; nt < 4; nt++)
#pragma unroll
            for (int j = 0; j < 4; j++) acc[mt][nt][j] = 0.f;

    const int lr = tid >> 2;
    const int ls = (tid & 3) * 8;

#define K3_LOAD(kc, buf)                                                                \
    do {                                                                                \
        int _k0 = kb + (kc) * 32;                                                       \
        const __half* _A = Ag + (size_t)m0 * 4096 + _k0;                                \
        const __half* _B = g_EFh + _k0;                                                 \
        CP_ASYNC16(smem_u32(&As[buf][lr][ls]), _A + (size_t)lr * 4096 + ls);            \
        CP_ASYNC16(smem_u32(&As[buf][lr + 64][ls]), _A + (size_t)(lr + 64) * 4096 + ls);\
        CP_ASYNC16(smem_u32(&Bs[buf][lr][ls]), _B + (size_t)lr * 4096 + ls);            \
    } while (0)

    K3_LOAD(0, 0); CP_COMMIT();
    K3_LOAD(1, 1); CP_COMMIT();

#pragma unroll
    for (int s = 0; s < 16; s++) {
        const int buf = s % 3;
        CP_WAITG1();
        __syncthreads();

        if (s + 2 < 16) K3_LOAD(s + 2, (s + 2) % 3);
        CP_COMMIT();

#pragma unroll
        for (int h = 0; h < 2; h++) {
            uint32_t af[2][4], bfr[4][2];
            const __half* Abase = &As[buf][x4_row][h * 16 + x4_col];
            const __half* Bbase = &Bs[buf][x4_row][h * 16 + x4_col];
#pragma unroll
            for (int mt = 0; mt < 2; mt++)
                ldsm_x4(af[mt][0], af[mt][1], af[mt][2], af[mt][3],
                        smem_u32(Abase + (wm + mt * 16) * K3_STRIDE));
#pragma unroll
            for (int pr = 0; pr < 2; pr++)
                ldsm_x4(bfr[2 * pr][0], bfr[2 * pr + 1][0],
                        bfr[2 * pr][1], bfr[2 * pr + 1][1],
                        smem_u32(Bbase + (wn + pr * 16) * K3_STRIDE));
#pragma unroll
            for (int mt = 0; mt < 2; mt++)
#pragma unroll
                for (int nt = 0; nt < 4; nt++)
                    mma_f16(acc[mt][nt], af[mt], bfr[nt]);
        }
    }
#undef K3_LOAD

#pragma unroll
    for (int mt = 0; mt < 2; mt++) {
        int row = m0 + wm + mt * 16 + g;
        float* p0 = &g_kvp[sp][(size_t)row * 64 + wn];
        float* p1 = p0 + 8 * 64;
#pragma unroll
        for (int nt = 0; nt < 4; nt++) {
            *(float2*)(p0 + nt * 8 + 2 * t4) = make_float2(acc[mt][nt][0], acc[mt][nt][1]);
            *(float2*)(p1 + nt * 8 + 2 * t4) = make_float2(acc[mt][nt][2], acc[mt][nt][3]);
        }
    }
}

__global__ __launch_bounds__(256) void k3r_reduce() {
    int i = blockIdx.x * 256 + threadIdx.x;
    float s = 0.f;
#pragma unroll
    for (int sp = 0; sp < 8; sp++) s += g_kvp[sp][i];
    g_kv[i] = s;
}

// ---------------------------------------------------------------------------
// K4: spatial attention on tensor cores (flash-style, fused softmax).
// ---------------------------------------------------------------------------
__global__ __launch_bounds__(128) void k4_mma(const float* __restrict__ temp2_sa) {
    __shared__ __align__(16) __half sQ[32][136];   // [d][n]
    __shared__ __align__(16) __half sK[64][40];    // [p][d], pre-scaled
    __shared__ __align__(16) __half sV[32][72];    // [d][p]
    __shared__ __align__(16) __half sO[32][136];   // [d][n]
    __shared__ float ivs[32];
    const int tid = threadIdx.x;
    const int lane = tid & 31, w = tid >> 5;
    const int n0 = blockIdx.x * 128;
    const int bh = blockIdx.y;
    const int h = bh & 7;
    const int g = lane >> 2, t4 = lane & 3;

    if (tid < 32) ivs[tid] = inv_norm(g_sumsq[bh * 32 + tid]);
    __syncthreads();
    const float temp = temp2_sa[h];

#pragma unroll
    for (int i = 0; i < 16; i++) {
        int u = tid + i * 128;
        int d = u >> 6, p = u & 63;
        sK[p][d] = __float2half(g_kv[bh * 2048 + d * 64 + p] * ivs[d] * temp);
        sV[d][p] = __float2half(g_kv[(64 + bh) * 2048 + d * 64 + p]);
    }
    const __half* qb = g_proj + (size_t)(bh * 32) * N_ + n0;
#pragma unroll
    for (int i = 0; i < 4; i++) {
        int u = tid + i * 128;
        int d = u >> 4, sg = u & 15;
        *(uint4*)&sQ[d][sg * 8] = *(const uint4*)(qb + (size_t)d * N_ + sg * 8);
    }
    __syncthreads();

    // ---- GEMM1: S = Q^T x Ksc  (M=32 rows/warp, N=64, K=32) ----
    const int a_d = (lane & 7) | (((lane >> 4) & 1) << 3);
    const int a_noff = ((lane >> 3) & 1) * 8;
    const int x4_row = lane & 15, x4_col = (lane >> 4) * 8;

    float acc[2][8][4];
#pragma unroll
    for (int mt = 0; mt < 2; mt++)
#pragma unroll
        for (int nt = 0; nt < 8; nt++)
#pragma unroll
            for (int j = 0; j < 4; j++) acc[mt][nt][j] = 0.f;

#pragma unroll
    for (int h2 = 0; h2 < 2; h2++) {
        uint32_t af[2][4], bfr[8][2];
#pragma unroll
        for (int mt = 0; mt < 2; mt++)
            ldsm_x4t(af[mt][0], af[mt][1], af[mt][2], af[mt][3],
                     smem_u32(&sQ[a_d + h2 * 16][w * 32 + mt * 16 + a_noff]));
#pragma unroll
        for (int pr = 0; pr < 4; pr++)
            ldsm_x4(bfr[2 * pr][0], bfr[2 * pr + 1][0],
                    bfr[2 * pr][1], bfr[2 * pr + 1][1],
                    smem_u32(&sK[pr * 16 + x4_row][x4_col + h2 * 16]));
#pragma unroll
        for (int mt = 0; mt < 2; mt++)
#pragma unroll
            for (int nt = 0; nt < 8; nt++)
                mma_f16(acc[mt][nt], af[mt], bfr[nt]);
    }

    // ---- softmax over p (64), rows spread over t4 quad ----
    float isr[2][2];
    uint32_t pa[2][4][4];
#pragma unroll
    for (int mt = 0; mt < 2; mt++) {
        float m0 = -1e30f, m1 = -1e30f;
#pragma unroll
        for (int nt = 0; nt < 8; nt++) {
            m0 = fmaxf(m0, fmaxf(acc[mt][nt][0], acc[mt][nt][1]));
            m1 = fmaxf(m1, fmaxf(acc[mt][nt][2], acc[mt][nt][3]));
        }
        m0 = fmaxf(m0, __shfl_xor_sync(0xffffffffu, m0, 1));
        m0 = fmaxf(m0, __shfl_xor_sync(0xffffffffu, m0, 2));
        m1 = fmaxf(m1, __shfl_xor_sync(0xffffffffu, m1, 1));
        m1 = fmaxf(m1, __shfl_xor_sync(0xffffffffu, m1, 2));
        float s0 = 0.f, s1 = 0.f;
#pragma unroll
        for (int nt = 0; nt < 8; nt++) {
            acc[mt][nt][0] = fexp(acc[mt][nt][0] - m0);
            acc[mt][nt][1] = fexp(acc[mt][nt][1] - m0);
            acc[mt][nt][2] = fexp(acc[mt][nt][2] - m1);
            acc[mt][nt][3] = fexp(acc[mt][nt][3] - m1);
            s0 += acc[mt][nt][0] + acc[mt][nt][1];
            s1 += acc[mt][nt][2] + acc[mt][nt][3];
        }
        s0 += __shfl_xor_sync(0xffffffffu, s0, 1);
        s0 += __shfl_xor_sync(0xffffffffu, s0, 2);
        s1 += __shfl_xor_sync(0xffffffffu, s1, 1);
        s1 += __shfl_xor_sync(0xffffffffu, s1, 2);
        isr[mt][0] = 1.f / s0;
        isr[mt][1] = 1.f / s1;
#pragma unroll
        for (int kk = 0; kk < 4; kk++) {
            __half2 h0 = __floats2half2_rn(acc[mt][2 * kk][0], acc[mt][2 * kk][1]);
            __half2 h1 = __floats2half2_rn(acc[mt][2 * kk][2], acc[mt][2 * kk][3]);
            __half2 h2a = __floats2half2_rn(acc[mt][2 * kk + 1][0], acc[mt][2 * kk + 1][1]);
            __half2 h3 = __floats2half2_rn(acc[mt][2 * kk + 1][2], acc[mt][2 * kk + 1][3]);
            pa[mt][kk][0] = *(uint32_t*)&h0;
            pa[mt][kk][1] = *(uint32_t*)&h1;
            pa[mt][kk][2] = *(uint32_t*)&h2a;
            pa[mt][kk][3] = *(uint32_t*)&h3;
        }
    }

    // ---- GEMM2: O = P x V^T  (M=32/warp, N=32 d, K=64 p) ----
    float o[2][4][4];
#pragma unroll
    for (int mt = 0; mt < 2; mt++)
#pragma unroll
        for (int nt = 0; nt < 4; nt++)
#pragma unroll
            for (int j = 0; j < 4; j++) o[mt][nt][j] = 0.f;

#pragma unroll
    for (int kk = 0; kk < 4; kk++) {
        uint32_t bfr[4][2];
#pragma unroll
        for (int pr = 0; pr < 2; pr++)
            ldsm_x4(bfr[2 * pr][0], bfr[2 * pr + 1][0],
                    bfr[2 * pr][1], bfr[2 * pr + 1][1],
                    smem_u32(&sV[pr * 16 + x4_row][x4_col + kk * 16]));
#pragma unroll
        for (int mt = 0; mt < 2; mt++)
#pragma unroll
            for (int nt = 0; nt < 4; nt++)
                mma_f16(o[mt][nt], pa[mt][kk], bfr[nt]);
    }

    // ---- scale by 1/sum, stage to sO [d][n], write out coalesced ----
#pragma unroll
    for (int mt = 0; mt < 2; mt++) {
        int r0 = w * 32 + mt * 16 + g;
#pragma unroll
        for (int nt = 0; nt < 4; nt++) {
            int d0 = nt * 8 + 2 * t4;
            sO[d0][r0]         = __float2half(o[mt][nt][0] * isr[mt][0]);
            sO[d0 + 1][r0]     = __float2half(o[mt][nt][1] * isr[mt][0]);
            sO[d0][r0 + 8]     = __float2half(o[mt][nt][2] * isr[mt][1]);
            sO[d0 + 1][r0 + 8] = __float2half(o[mt][nt][3] * isr[mt][1]);
        }
    }
    __syncthreads();
    __half* ob = g_xsa + (size_t)(bh * 32) * N_ + n0;
#pragma unroll
    for (int i = 0; i < 4; i++) {
        int u = tid + i * 128;
        int d = u >> 4, sg = u & 15;
        *(uint4*)(ob + (size_t)d * N_ + sg * 8) = *(uint4*)&sO[d][sg * 8];
    }
}

// ---------------------------------------------------------------------------
// K5: channel gram, split over n (4 CTAs per bh) with fp32 atomics.
// ---------------------------------------------------------------------------
__global__ __launch_bounds__(256) void k5_gram() {
    int bh = blockIdx.x;
    int sp = blockIdx.y;
    __shared__ float qcs[32][133], kcs[32][133];
    int tid = threadIdx.x;
    int ddp = tid >> 4, ep = tid & 15;
    float a00 = 0.f, a01 = 0.f, a10 = 0.f, a11 = 0.f;
    const __half* qsrc = g_proj + ((size_t)3 * 2048 + bh * 32) * N_;
    const __half* ksrc = g_proj + ((size_t)4 * 2048 + bh * 32) * N_;

    for (int cc = 0; cc < 8; cc++) {
        int c0 = sp * 1024 + cc * 128;
#pragma unroll
        for (int i = 0; i < 16; i++) {
            int f = tid + i * 256;
            int r = f >> 7, j = f & 127;
            qcs[r][j] = __half2float(qsrc[(size_t)r * N_ + c0 + j]);
            kcs[r][j] = __half2float(ksrc[(size_t)r * N_ + c0 + j]);
        }
        __syncthreads();
#pragma unroll 4
        for (int nn = 0; nn < 128; nn++) {
            float q0 = qcs[2 * ddp][nn], q1 = qcs[2 * ddp + 1][nn];
            float k0 = kcs[2 * ep][nn],  k1 = kcs[2 * ep + 1][nn];
            a00 += q0 * k0; a01 += q0 * k1;
            a10 += q1 * k0; a11 += q1 * k1;
        }
        __syncthreads();
    }
    float* gb = &g_gram[bh * 1024];
    atomicAdd(&gb[(2 * ddp) * 32 + 2 * ep], a00);
    atomicAdd(&gb[(2 * ddp) * 32 + 2 * ep + 1], a01);
    atomicAdd(&gb[(2 * ddp + 1) * 32 + 2 * ep], a10);
    atomicAdd(&gb[(2 * ddp + 1) * 32 + 2 * ep + 1], a11);
}

// K5s: scale + softmax of the gram matrix -> g_attn
__global__ __launch_bounds__(256) void k5s_softmax(const float* __restrict__ temp_sc) {
    int bh = blockIdx.x;
    int h = bh & 7;
    __shared__ float att[32][33];
    __shared__ float ivqs[32], ivks[32];
    int tid = threadIdx.x;
    if (tid < 32) ivqs[tid] = inv_norm(g_sumsq[2048 + bh * 32 + tid]);
    else if (tid < 64) ivks[tid - 32] = inv_norm(g_sumsq[4096 + bh * 32 + tid - 32]);
    __syncthreads();
    float temp = temp_sc[h];
#pragma unroll
    for (int i = 0; i < 4; i++) {
        int idx = tid + i * 256;
        int r = idx >> 5, c = idx & 31;
        att[r][c] = g_gram[bh * 1024 + idx] * ivqs[r] * ivks[c] * temp;
    }
    __syncthreads();
    int w = tid >> 5, l = tid & 31;
#pragma unroll
    for (int r0 = 0; r0 < 4; r0++) {
        int r = w * 4 + r0;
        float v = att[r][l];
        float m = v;
#pragma unroll
        for (int o = 16; o > 0; o >>= 1) m = fmaxf(m, __shfl_xor_sync(0xffffffffu, m, o));
        float e = fexp(v - m);
        float sum = e;
#pragma unroll
        for (int o = 16; o > 0; o >>= 1) sum += __shfl_xor_sync(0xffffffffu, sum, o);
        g_attn[bh * 1024 + r * 32 + l] = e / sum;
    }
}

// ---------------------------------------------------------------------------
// K6: combine
// ---------------------------------------------------------------------------
__global__ __launch_bounds__(128) void k6_combine(float* __restrict__ out) {
    int ch = blockIdx.x;
    int bh = blockIdx.y;
    int b = bh >> 3, h = bh & 7;
    __shared__ float vcs[32][128];
    __shared__ float sas[128][33];
    __shared__ float att[1024];
    int tid = threadIdx.x;

    const __half* vsrc = g_proj + ((size_t)5 * 2048 + bh * 32) * N_ + ch * 128;
#pragma unroll
    for (int i = 0; i < 32; i++) {
        int f = tid + i * 128;
        int e = f >> 7, j = f & 127;
        vcs[e][j] = __half2float(vsrc[(size_t)e * N_ + j]);
    }
#pragma unroll
    for (int i = 0; i < 32; i++) {
        int f = tid + i * 128;
        int tp = f >> 5, dc = f & 31;
        sas[tp][dc] = __half2float(g_xsa[((size_t)(b * 8 + (tp >> 4)) * 32 + ch) * N_ +
                                         (tp & 15) * 256 + h * 32 + dc]);
    }
#pragma unroll
    for (int i = 0; i < 8; i++) att[tid + i * 128] = g_attn[bh * 1024 + tid + i * 128];
    __syncthreads();

    float acc[32];
#pragma unroll
    for (int dc = 0; dc < 32; dc++) acc[dc] = 0.f;
#pragma unroll 4
    for (int e = 0; e < 32; e++) {
        float v = vcs[e][tid];
#pragma unroll
        for (int dc = 0; dc < 32; dc++) acc[dc] += att[dc * 32 + e] * v;
    }
    float* ob = out + (size_t)(b * 256 + h * 32) * N_ + ch * 128 + tid;
#pragma unroll
    for (int dc = 0; dc < 32; dc++) ob[(size_t)dc * N_] = acc[dc] + sas[tid][dc];
}

// ---------------------------------------------------------------------------
extern "C" void kernel_launch(void* const* d_in, const int* in_sizes, int n_in,
                              void* d_out, int out_size) {
    const float* x    = (const float*)d_in[0];
    const float* Wsa  = (const float*)d_in[1];
    const float* EF   = (const float*)d_in[2];
    const float* t2sa = (const float*)d_in[3];
    const float* Wsc  = (const float*)d_in[4];
    const float* tsc  = (const float*)d_in[5];
    float* out = (float*)d_out;

    const int k1_smem = 3 * 2 * K1_TILE_HALVES * (int)sizeof(__half);  // 61440
    cudaFuncSetAttribute(k1_mma, cudaFuncAttributeMaxDynamicSharedMemorySize, k1_smem);

    k0w_pack<<<1536, 256>>>(Wsa, Wsc);
    k0x_pack<<<dim3(32, 8), 128>>>(x);
    k0e_pack<<<64, 256>>>(EF);
    k1_mma<<<dim3(32, 12, 8), 256, k1_smem>>>();
    k3_mma<<<dim3(32, 8), 256>>>();
    k3r_reduce<<<1024, 256>>>();
    k4_mma<<<dim3(32, 64), 128>>>(t2sa);
    k5_gram<<<dim3(64, 4), 256>>>();
    k5s_softmax<<<64, 256>>>(tsc);
    k6_combine<<<dim3(32, 64), 128>>>(out);
}

// round 16
// speedup vs baseline: 1.1674x; 1.1674x over previous
#include <cuda_runtime.h>
#include <cuda_bf16.h>
#include <cuda_fp16.h>
#include <math.h>
#include <stdint.h>

// Problem constants
#define B_ 8
#define C_ 256
#define N_ 4096
#define H_ 8
#define D_ 32
#define P_ 64

// Scratch (device globals; allocation-free contract)
// g_proj layout: [slab][b][row256][n] (fp16), slab: 0=q_sa,1=k_sa,2=v_sa,3=q_c,4=k_c,5=v_c
__device__ __half g_proj[6u * 8u * 256u * 4096u];     // 100 MB
__device__ float g_sumsq[3 * 2048];                   // row sum-of-squares (atomic)
__device__ float g_kvp[8][2 * 64 * 32 * 64];          // K-split partials [sp][row*64+p]
__device__ float g_kv[2 * 64 * 32 * 64];
__device__ float g_gram[64 * 32 * 32];                // channel gram partial sums (atomic)
__device__ float g_attn[64 * 32 * 32];
__device__ __half g_xsa[8u * 8u * 32u * 4096u];       // spatial out [b][h][d][n], fp16

// fp16 operands for the tensor-core GEMMs
__device__ __half g_Wh[1536 * 256];
__device__ __half g_xh[8u * 4096u * 256u];            // [b][n][c]  (transposed)
__device__ __half g_EFh[64 * 4096];                   // EF transposed: [p][n]

// ---------------------------------------------------------------------------
// helpers
// ---------------------------------------------------------------------------
__device__ __forceinline__ uint32_t smem_u32(const void* p) {
    uint32_t a;
    asm("{ .reg .u64 t; cvta.to.shared.u64 t, %1; cvt.u32.u64 %0, t; }" : "=r"(a) : "l"(p));
    return a;
}
#define CP_ASYNC16(dst, src) \
    asm volatile("cp.async.cg.shared.global [%0], [%1], 16;" :: "r"(dst), "l"(src))
#define CP_COMMIT() asm volatile("cp.async.commit_group;" ::: "memory")
#define CP_WAITG1() asm volatile("cp.async.wait_group 1;" ::: "memory")

__device__ __forceinline__ void mma_f16(float* d, const uint32_t* a, const uint32_t* bb) {
    asm volatile(
        "mma.sync.aligned.m16n8k16.row.col.f32.f16.f16.f32 "
        "{%0,%1,%2,%3}, {%4,%5,%6,%7}, {%8,%9}, {%0,%1,%2,%3};"
        : "+f"(d[0]), "+f"(d[1]), "+f"(d[2]), "+f"(d[3])
        : "r"(a[0]), "r"(a[1]), "r"(a[2]), "r"(a[3]), "r"(bb[0]), "r"(bb[1]));
}
__device__ __forceinline__ void ldsm_x4(uint32_t& r0, uint32_t& r1, uint32_t& r2,
                                        uint32_t& r3, uint32_t addr) {
    asm volatile("ldmatrix.sync.aligned.m8n8.x4.shared.b16 {%0,%1,%2,%3}, [%4];"
                 : "=r"(r0), "=r"(r1), "=r"(r2), "=r"(r3) : "r"(addr));
}
__device__ __forceinline__ void ldsm_x4t(uint32_t& r0, uint32_t& r1, uint32_t& r2,
                                         uint32_t& r3, uint32_t addr) {
    asm volatile("ldmatrix.sync.aligned.m8n8.x4.trans.shared.b16 {%0,%1,%2,%3}, [%4];"
                 : "=r"(r0), "=r"(r1), "=r"(r2), "=r"(r3) : "r"(addr));
}

// FFMA-only exp (avoids MUFU pipe), ~2e-6 relative accuracy.
__device__ __forceinline__ float fexp(float x) {
    const float L2E = 1.4426950408889634f;
    float t = fmaf(x, L2E, 12582912.0f);
    float n = t - 12582912.0f;
    float f = fmaf(x, L2E, -n);
    float p = 1.33978035e-3f;
    p = fmaf(p, f, 9.67770915e-3f);
    p = fmaf(p, f, 5.55041086e-2f);
    p = fmaf(p, f, 2.40226507e-1f);
    p = fmaf(p, f, 6.93147182e-1f);
    p = fmaf(p, f, 1.0f);
    int e = __float2int_rn(n);
    if (e < -126) e = -126;
    if (e > 126) e = 126;
    return __int_as_float((e + 127) << 23) * p;
}

__device__ __forceinline__ float inv_norm(float ss) {
    return 1.f / fmaxf(sqrtf(ss), 1e-12f);
}

// ---------------------------------------------------------------------------
// K0w: pack weights into fp16 (GEMM row order) + zero accumulators.
// ---------------------------------------------------------------------------
__global__ __launch_bounds__(256) void k0w_pack(const float* __restrict__ Wsa,
                                                const float* __restrict__ Wsc) {
    int e = blockIdx.x * 256 + threadIdx.x;       // 0 .. 393215
    if (e < 3 * 2048) g_sumsq[e] = 0.f;
    if (e < 64 * 32 * 32) g_gram[e] = 0.f;
    int r = e >> 8, c = e & 255;
    int p = (r >= 768) ? 1 : 0;
    int rr = r - p * 768;
    int t = rr >> 8;
    const float* Wp = p ? Wsc : Wsa;
    int srow = rr + ((p == 0 && t == 2) ? 256 : 0);
    g_Wh[e] = __float2half(Wp[(size_t)srow * 256 + c]);
}

// ---------------------------------------------------------------------------
// K0x: transpose x [b][c][n] -> [b][n][c], fp16.
// ---------------------------------------------------------------------------
__global__ __launch_bounds__(128) void k0x_pack(const float* __restrict__ x) {
    int n0 = blockIdx.x * 128;
    int b = blockIdx.y;
    __shared__ float sm[64][132];
    int tid = threadIdx.x;
    const float* xb = x + (size_t)b * C_ * N_;

    for (int c0 = 0; c0 < 256; c0 += 64) {
#pragma unroll
        for (int i = 0; i < 16; i++) {
            int u = tid + i * 128;
            int c = u >> 5, nq = u & 31;
            *(float4*)&sm[c][nq * 4] =
                *(const float4*)(xb + (size_t)(c0 + c) * N_ + n0 + nq * 4);
        }
        __syncthreads();
        uint32_t buf[32];
#pragma unroll
        for (int c = 0; c < 64; c += 2) {
            __half2 hv = __floats2half2_rn(sm[c][tid], sm[c + 1][tid]);
            buf[c >> 1] = *(uint32_t*)&hv;
        }
        size_t obase = ((size_t)b * 4096 + n0 + tid) * 256 + c0;
#pragma unroll
        for (int j = 0; j < 8; j++)
            *(uint4*)&g_xh[obase + j * 8] = *(uint4*)&buf[j * 4];
        __syncthreads();
    }
}

// ---------------------------------------------------------------------------
// K0e: transpose EF [n][p] fp32 -> g_EFh [p][n] fp16.
// ---------------------------------------------------------------------------
__global__ __launch_bounds__(256) void k0e_pack(const float* __restrict__ EF) {
    __shared__ float tile[64][65];
    int n0 = blockIdx.x * 64;
    int tid = threadIdx.x;
#pragma unroll
    for (int i = 0; i < 16; i++) {
        int u = tid + i * 256;
        int r = u >> 6, c = u & 63;
        tile[c][r] = EF[(size_t)(n0 + r) * 64 + c];
    }
    __syncthreads();
#pragma unroll
    for (int i = 0; i < 16; i++) {
        int u = tid + i * 256;
        int p = u >> 6, j = u & 63;
        g_EFh[(size_t)p * 4096 + n0 + j] = __float2half(tile[p][j]);
    }
}

// ---------------------------------------------------------------------------
// K1: fp16 mma.sync GEMM; dynamic 3-stage pipeline (low regs), x4-paired B.
// CTA 128m x 128n; 8 warps (2m x 4n); 8 k32 steps.
// ---------------------------------------------------------------------------
#define K1_TSTRIDE 40
#define K1_TILE_HALVES (128 * K1_TSTRIDE)

__global__ __launch_bounds__(256) void k1_mma() {
    extern __shared__ __half sm1[];
    const int n0 = blockIdx.x * 128;
    const int my = blockIdx.y;                  // 0..11
    const int b  = blockIdx.z;
    const int m0 = my * 128;

    const int tid = threadIdx.x;
    const int wid = tid >> 5, lane = tid & 31;
    const int wm = (wid & 1) * 64, wn = (wid >> 1) * 32;
    const int g = lane >> 2, t4 = lane & 3;

    const int x4_row = lane & 15, x4_col = (lane >> 4) * 8;

#define TILE(buf, t) (sm1 + ((buf) * 2 + (t)) * K1_TILE_HALVES)

    float acc[4][4][4];
#pragma unroll
    for (int mt = 0; mt < 4; mt++)
#pragma unroll
        for (int nt = 0; nt < 4; nt++)
#pragma unroll
            for (int j = 0; j < 4; j++) acc[mt][nt][j] = 0.f;

    const int lr0 = tid >> 2;
    const int ls0 = (tid & 3) * 8;

#define LOAD_STEP(kc, buf)                                                              \
    do {                                                                                \
        int _k0 = (kc) * 32;                                                            \
        const __half* _A = g_Wh + (size_t)m0 * 256 + _k0;                               \
        const __half* _B = g_xh + ((size_t)b * 4096 + n0) * 256 + _k0;                  \
        CP_ASYNC16(smem_u32(TILE(buf,0) + lr0 * K1_TSTRIDE + ls0), _A + (size_t)lr0 * 256 + ls0); \
        CP_ASYNC16(smem_u32(TILE(buf,0) + (lr0+64) * K1_TSTRIDE + ls0), _A + (size_t)(lr0+64) * 256 + ls0); \
        CP_ASYNC16(smem_u32(TILE(buf,1) + lr0 * K1_TSTRIDE + ls0), _B + (size_t)lr0 * 256 + ls0); \
        CP_ASYNC16(smem_u32(TILE(buf,1) + (lr0+64) * K1_TSTRIDE + ls0), _B + (size_t)(lr0+64) * 256 + ls0); \
    } while (0)

    LOAD_STEP(0, 0); CP_COMMIT();
    LOAD_STEP(1, 1); CP_COMMIT();

    for (int s = 0; s < 8; s++) {
        const int buf = s % 3;
        CP_WAITG1();
        __syncthreads();

        if (s + 2 < 8) LOAD_STEP(s + 2, (s + 2) % 3);
        CP_COMMIT();

#pragma unroll
        for (int h = 0; h < 2; h++) {
            uint32_t af[4][4], bfr[4][2];
            const __half* Abase = TILE(buf, 0) + (size_t)x4_row * K1_TSTRIDE + h * 16 + x4_col;
            const __half* Bbase = TILE(buf, 1) + (size_t)x4_row * K1_TSTRIDE + h * 16 + x4_col;
#pragma unroll
            for (int mt = 0; mt < 4; mt++)
                ldsm_x4(af[mt][0], af[mt][1], af[mt][2], af[mt][3],
                        smem_u32(Abase + (wm + mt * 16) * K1_TSTRIDE));
#pragma unroll
            for (int pr = 0; pr < 2; pr++)
                ldsm_x4(bfr[2 * pr][0], bfr[2 * pr + 1][0],
                        bfr[2 * pr][1], bfr[2 * pr + 1][1],
                        smem_u32(Bbase + (wn + pr * 16) * K1_TSTRIDE));
#pragma unroll
            for (int mt = 0; mt < 4; mt++)
#pragma unroll
                for (int nt = 0; nt < 4; nt++)
                    mma_f16(acc[mt][nt], af[mt], bfr[nt]);
        }
    }
#undef LOAD_STEP
#undef TILE

    // epilogue -> g_proj (fp16) + fused sumsq for slabs 0,3,4
    const int slab = my >> 1;
    const int rb = (my & 1) * 128;
    const int which = (slab == 0) ? 0 : (slab == 3 ? 1 : (slab == 4 ? 2 : -1));
#pragma unroll
    for (int mt = 0; mt < 4; mt++) {
        int r0 = rb + wm + mt * 16 + g;
        __half* p0 = g_proj + (((size_t)slab * 8 + b) * 256 + r0) * (size_t)N_ + n0 + wn;
        __half* p1 = p0 + 8 * (size_t)N_;
        float ss0 = 0.f, ss1 = 0.f;
#pragma unroll
        for (int nt = 0; nt < 4; nt++) {
            float a0 = acc[mt][nt][0], a1 = acc[mt][nt][1];
            float a2 = acc[mt][nt][2], a3 = acc[mt][nt][3];
            *(__half2*)(p0 + nt * 8 + 2 * t4) = __floats2half2_rn(a0, a1);
            *(__half2*)(p1 + nt * 8 + 2 * t4) = __floats2half2_rn(a2, a3);
            ss0 += a0 * a0 + a1 * a1;
            ss1 += a2 * a2 + a3 * a3;
        }
        if (which >= 0) {
            ss0 += __shfl_xor_sync(0xffffffffu, ss0, 1);
            ss0 += __shfl_xor_sync(0xffffffffu, ss0, 2);
            ss1 += __shfl_xor_sync(0xffffffffu, ss1, 1);
            ss1 += __shfl_xor_sync(0xffffffffu, ss1, 2);
            if (t4 == 0) {
                int row = b * 256 + r0;
                atomicAdd(&g_sumsq[which * 2048 + row], ss0);
                atomicAdd(&g_sumsq[which * 2048 + row + 8], ss1);
            }
        }
    }
}

// ---------------------------------------------------------------------------
// K3: Linformer projection GEMM; dynamic 3-stage pipeline, x4-paired B.
// CTA 128m x 64n; 8 warps (4m x 2n); 16 k32 steps; K-split 8.
// ---------------------------------------------------------------------------
#define K3_STRIDE 40
__global__ __launch_bounds__(256) void k3_mma() {
    __shared__ __half As[3][128][K3_STRIDE];
    __shared__ __half Bs[3][64][K3_STRIDE];
    const int m0 = blockIdx.x * 128;
    const int sp = blockIdx.y;
    const int kb = sp * 512;

    const int tid = threadIdx.x;
    const int wid = tid >> 5, lane = tid & 31;
    const int wm = (wid >> 1) * 32;
    const int wn = (wid & 1) * 32;
    const int g = lane >> 2, t4 = lane & 3;

    const int x4_row = lane & 15, x4_col = (lane >> 4) * 8;

    const __half* Ag = g_proj + (size_t)2048 * N_;

    float acc[2][4][4];
#pragma unroll
    for (int mt = 0; mt < 2; mt++)
#pragma unroll
        for (int nt = 0; nt < 4; nt++)
#pragma unroll
            for (int j = 0; j < 4; j++) acc[mt][nt][j] = 0.f;

    const int lr = tid >> 2;
    const int ls = (tid & 3) * 8;

#define K3_LOAD(kc, buf)                                                                \
    do {                                                                                \
        int _k0 = kb + (kc) * 32;                                                       \
        const __half* _A = Ag + (size_t)m0 * 4096 + _k0;                                \
        const __half* _B = g_EFh + _k0;                                                 \
        CP_ASYNC16(smem_u32(&As[buf][lr][ls]), _A + (size_t)lr * 4096 + ls);            \
        CP_ASYNC16(smem_u32(&As[buf][lr + 64][ls]), _A + (size_t)(lr + 64) * 4096 + ls);\
        CP_ASYNC16(smem_u32(&Bs[buf][lr][ls]), _B + (size_t)lr * 4096 + ls);            \
    } while (0)

    K3_LOAD(0, 0); CP_COMMIT();
    K3_LOAD(1, 1); CP_COMMIT();

    for (int s = 0; s < 16; s++) {
        const int buf = s % 3;
        CP_WAITG1();
        __syncthreads();

        if (s + 2 < 16) K3_LOAD(s + 2, (s + 2) % 3);
        CP_COMMIT();

#pragma unroll
        for (int h = 0; h < 2; h++) {
            uint32_t af[2][4], bfr[4][2];
            const __half* Abase = &As[buf][x4_row][h * 16 + x4_col];
            const __half* Bbase = &Bs[buf][x4_row][h * 16 + x4_col];
#pragma unroll
            for (int mt = 0; mt < 2; mt++)
                ldsm_x4(af[mt][0], af[mt][1], af[mt][2], af[mt][3],
                        smem_u32(Abase + (wm + mt * 16) * K3_STRIDE));
#pragma unroll
            for (int pr = 0; pr < 2; pr++)
                ldsm_x4(bfr[2 * pr][0], bfr[2 * pr + 1][0],
                        bfr[2 * pr][1], bfr[2 * pr + 1][1],
                        smem_u32(Bbase + (wn + pr * 16) * K3_STRIDE));
#pragma unroll
            for (int mt = 0; mt < 2; mt++)
#pragma unroll
                for (int nt = 0; nt < 4; nt++)
                    mma_f16(acc[mt][nt], af[mt], bfr[nt]);
        }
    }
#undef K3_LOAD

#pragma unroll
    for (int mt = 0; mt < 2; mt++) {
        int row = m0 + wm + mt * 16 + g;
        float* p0 = &g_kvp[sp][(size_t)row * 64 + wn];
        float* p1 = p0 + 8 * 64;
#pragma unroll
        for (int nt = 0; nt < 4; nt++) {
            *(float2*)(p0 + nt * 8 + 2 * t4) = make_float2(acc[mt][nt][0], acc[mt][nt][1]);
            *(float2*)(p1 + nt * 8 + 2 * t4) = make_float2(acc[mt][nt][2], acc[mt][nt][3]);
        }
    }
}

__global__ __launch_bounds__(256) void k3r_reduce() {
    int i = blockIdx.x * 256 + threadIdx.x;
    float s = 0.f;
#pragma unroll
    for (int sp = 0; sp < 8; sp++) s += g_kvp[sp][i];
    g_kv[i] = s;
}

// ---------------------------------------------------------------------------
// K4: spatial attention on tensor cores (flash-style, fused softmax).
// ---------------------------------------------------------------------------
__global__ __launch_bounds__(128) void k4_mma(const float* __restrict__ temp2_sa) {
    __shared__ __align__(16) __half sQ[32][136];   // [d][n]
    __shared__ __align__(16) __half sK[64][40];    // [p][d], pre-scaled
    __shared__ __align__(16) __half sV[32][72];    // [d][p]
    __shared__ __align__(16) __half sO[32][136];   // [d][n]
    __shared__ float ivs[32];
    const int tid = threadIdx.x;
    const int lane = tid & 31, w = tid >> 5;
    const int n0 = blockIdx.x * 128;
    const int bh = blockIdx.y;
    const int h = bh & 7;
    const int g = lane >> 2, t4 = lane & 3;

    if (tid < 32) ivs[tid] = inv_norm(g_sumsq[bh * 32 + tid]);
    __syncthreads();
    const float temp = temp2_sa[h];

#pragma unroll
    for (int i = 0; i < 16; i++) {
        int u = tid + i * 128;
        int d = u >> 6, p = u & 63;
        sK[p][d] = __float2half(g_kv[bh * 2048 + d * 64 + p] * ivs[d] * temp);
        sV[d][p] = __float2half(g_kv[(64 + bh) * 2048 + d * 64 + p]);
    }
    const __half* qb = g_proj + (size_t)(bh * 32) * N_ + n0;
#pragma unroll
    for (int i = 0; i < 4; i++) {
        int u = tid + i * 128;
        int d = u >> 4, sg = u & 15;
        *(uint4*)&sQ[d][sg * 8] = *(const uint4*)(qb + (size_t)d * N_ + sg * 8);
    }
    __syncthreads();

    // ---- GEMM1: S = Q^T x Ksc  (M=32 rows/warp, N=64, K=32) ----
    const int a_d = (lane & 7) | (((lane >> 4) & 1) << 3);
    const int a_noff = ((lane >> 3) & 1) * 8;
    const int x4_row = lane & 15, x4_col = (lane >> 4) * 8;

    float acc[2][8][4];
#pragma unroll
    for (int mt = 0; mt < 2; mt++)
#pragma unroll
        for (int nt = 0; nt < 8; nt++)
#pragma unroll
            for (int j = 0; j < 4; j++) acc[mt][nt][j] = 0.f;

#pragma unroll
    for (int h2 = 0; h2 < 2; h2++) {
        uint32_t af[2][4], bfr[8][2];
#pragma unroll
        for (int mt = 0; mt < 2; mt++)
            ldsm_x4t(af[mt][0], af[mt][1], af[mt][2], af[mt][3],
                     smem_u32(&sQ[a_d + h2 * 16][w * 32 + mt * 16 + a_noff]));
#pragma unroll
        for (int pr = 0; pr < 4; pr++)
            ldsm_x4(bfr[2 * pr][0], bfr[2 * pr + 1][0],
                    bfr[2 * pr][1], bfr[2 * pr + 1][1],
                    smem_u32(&sK[pr * 16 + x4_row][x4_col + h2 * 16]));
#pragma unroll
        for (int mt = 0; mt < 2; mt++)
#pragma unroll
            for (int nt = 0; nt < 8; nt++)
                mma_f16(acc[mt][nt], af[mt], bfr[nt]);
    }

    // ---- softmax over p (64), rows spread over t4 quad ----
    float isr[2][2];
    uint32_t pa[2][4][4];
#pragma unroll
    for (int mt = 0; mt < 2; mt++) {
        float m0 = -1e30f, m1 = -1e30f;
#pragma unroll
        for (int nt = 0; nt < 8; nt++) {
            m0 = fmaxf(m0, fmaxf(acc[mt][nt][0], acc[mt][nt][1]));
            m1 = fmaxf(m1, fmaxf(acc[mt][nt][2], acc[mt][nt][3]));
        }
        m0 = fmaxf(m0, __shfl_xor_sync(0xffffffffu, m0, 1));
        m0 = fmaxf(m0, __shfl_xor_sync(0xffffffffu, m0, 2));
        m1 = fmaxf(m1, __shfl_xor_sync(0xffffffffu, m1, 1));
        m1 = fmaxf(m1, __shfl_xor_sync(0xffffffffu, m1, 2));
        float s0 = 0.f, s1 = 0.f;
#pragma unroll
        for (int nt = 0; nt < 8; nt++) {
            acc[mt][nt][0] = fexp(acc[mt][nt][0] - m0);
            acc[mt][nt][1] = fexp(acc[mt][nt][1] - m0);
            acc[mt][nt][2] = fexp(acc[mt][nt][2] - m1);
            acc[mt][nt][3] = fexp(acc[mt][nt][3] - m1);
            s0 += acc[mt][nt][0] + acc[mt][nt][1];
            s1 += acc[mt][nt][2] + acc[mt][nt][3];
        }
        s0 += __shfl_xor_sync(0xffffffffu, s0, 1);
        s0 += __shfl_xor_sync(0xffffffffu, s0, 2);
        s1 += __shfl_xor_sync(0xffffffffu, s1, 1);
        s1 += __shfl_xor_sync(0xffffffffu, s1, 2);
        isr[mt][0] = 1.f / s0;
        isr[mt][1] = 1.f / s1;
#pragma unroll
        for (int kk = 0; kk < 4; kk++) {
            __half2 h0 = __floats2half2_rn(acc[mt][2 * kk][0], acc[mt][2 * kk][1]);
            __half2 h1 = __floats2half2_rn(acc[mt][2 * kk][2], acc[mt][2 * kk][3]);
            __half2 h2a = __floats2half2_rn(acc[mt][2 * kk + 1][0], acc[mt][2 * kk + 1][1]);
            __half2 h3 = __floats2half2_rn(acc[mt][2 * kk + 1][2], acc[mt][2 * kk + 1][3]);
            pa[mt][kk][0] = *(uint32_t*)&h0;
            pa[mt][kk][1] = *(uint32_t*)&h1;
            pa[mt][kk][2] = *(uint32_t*)&h2a;
            pa[mt][kk][3] = *(uint32_t*)&h3;
        }
    }

    // ---- GEMM2: O = P x V^T  (M=32/warp, N=32 d, K=64 p) ----
    float o[2][4][4];
#pragma unroll
    for (int mt = 0; mt < 2; mt++)
#pragma unroll
        for (int nt = 0; nt < 4; nt++)
#pragma unroll
            for (int j = 0; j < 4; j++) o[mt][nt][j] = 0.f;

#pragma unroll
    for (int kk = 0; kk < 4; kk++) {
        uint32_t bfr[4][2];
#pragma unroll
        for (int pr = 0; pr < 2; pr++)
            ldsm_x4(bfr[2 * pr][0], bfr[2 * pr + 1][0],
                    bfr[2 * pr][1], bfr[2 * pr + 1][1],
                    smem_u32(&sV[pr * 16 + x4_row][x4_col + kk * 16]));
#pragma unroll
        for (int mt = 0; mt < 2; mt++)
#pragma unroll
            for (int nt = 0; nt < 4; nt++)
                mma_f16(o[mt][nt], pa[mt][kk], bfr[nt]);
    }

    // ---- scale by 1/sum, stage to sO [d][n], write out coalesced ----
#pragma unroll
    for (int mt = 0; mt < 2; mt++) {
        int r0 = w * 32 + mt * 16 + g;
#pragma unroll
        for (int nt = 0; nt < 4; nt++) {
            int d0 = nt * 8 + 2 * t4;
            sO[d0][r0]         = __float2half(o[mt][nt][0] * isr[mt][0]);
            sO[d0 + 1][r0]     = __float2half(o[mt][nt][1] * isr[mt][0]);
            sO[d0][r0 + 8]     = __float2half(o[mt][nt][2] * isr[mt][1]);
            sO[d0 + 1][r0 + 8] = __float2half(o[mt][nt][3] * isr[mt][1]);
        }
    }
    __syncthreads();
    __half* ob = g_xsa + (size_t)(bh * 32) * N_ + n0;
#pragma unroll
    for (int i = 0; i < 4; i++) {
        int u = tid + i * 128;
        int d = u >> 4, sg = u & 15;
        *(uint4*)(ob + (size_t)d * N_ + sg * 8) = *(uint4*)&sO[d][sg * 8];
    }
}

// ---------------------------------------------------------------------------
// K5: channel gram on tensor cores. Grid (bh, 4 n-splits), 256 threads.
// Warp w owns k16 slice w of each 128-token chunk; fp32 accum across 8 chunks;
// smem cross-warp reduce; one atomicAdd per element per CTA.
// ---------------------------------------------------------------------------
__global__ __launch_bounds__(256) void k5_mma() {
    int bh = blockIdx.x;
    int sp = blockIdx.y;
    __shared__ __align__(16) __half qcs[32][136], kcs[32][136];
    __shared__ float red[8][32][33];
    int tid = threadIdx.x;
    int w = tid >> 5, lane = tid & 31;
    const int x4_row = lane & 15, x4_col = (lane >> 4) * 8;
    const int g = lane >> 2, t4 = lane & 3;
    const __half* qsrc = g_proj + ((size_t)3 * 2048 + bh * 32) * N_;
    const __half* ksrc = g_proj + ((size_t)4 * 2048 + bh * 32) * N_;

    float acc[2][4][4];
#pragma unroll
    for (int mt = 0; mt < 2; mt++)
#pragma unroll
        for (int nt = 0; nt < 4; nt++)
#pragma unroll
            for (int j = 0; j < 4; j++) acc[mt][nt][j] = 0.f;

    for (int cc = 0; cc < 8; cc++) {
        int c0 = sp * 1024 + cc * 128;
#pragma unroll
        for (int i = 0; i < 2; i++) {
            int u = tid + i * 256;
            int r = u >> 4, sg = u & 15;
            *(uint4*)&qcs[r][sg * 8] = *(const uint4*)(qsrc + (size_t)r * N_ + c0 + sg * 8);
            *(uint4*)&kcs[r][sg * 8] = *(const uint4*)(ksrc + (size_t)r * N_ + c0 + sg * 8);
        }
        __syncthreads();
        uint32_t af[2][4], bfr[4][2];
#pragma unroll
        for (int mt = 0; mt < 2; mt++)
            ldsm_x4(af[mt][0], af[mt][1], af[mt][2], af[mt][3],
                    smem_u32(&qcs[mt * 16 + x4_row][w * 16 + x4_col]));
#pragma unroll
        for (int pr = 0; pr < 2; pr++)
            ldsm_x4(bfr[2 * pr][0], bfr[2 * pr + 1][0],
                    bfr[2 * pr][1], bfr[2 * pr + 1][1],
                    smem_u32(&kcs[pr * 16 + x4_row][w * 16 + x4_col]));
#pragma unroll
        for (int mt = 0; mt < 2; mt++)
#pragma unroll
            for (int nt = 0; nt < 4; nt++)
                mma_f16(acc[mt][nt], af[mt], bfr[nt]);
        __syncthreads();
    }

    // store per-warp partials, reduce across warps, one atomic per element
#pragma unroll
    for (int mt = 0; mt < 2; mt++) {
        int r = mt * 16 + g;
#pragma unroll
        for (int nt = 0; nt < 4; nt++) {
            int c = nt * 8 + 2 * t4;
            red[w][r][c]         = acc[mt][nt][0];
            red[w][r][c + 1]     = acc[mt][nt][1];
            red[w][r + 8][c]     = acc[mt][nt][2];
            red[w][r + 8][c + 1] = acc[mt][nt][3];
        }
    }
    __syncthreads();
#pragma unroll
    for (int i = 0; i < 4; i++) {
        int idx = tid + i * 256;
        int r = idx >> 5, c = idx & 31;
        float s = 0.f;
#pragma unroll
        for (int ww = 0; ww < 8; ww++) s += red[ww][r][c];
        atomicAdd(&g_gram[bh * 1024 + idx], s);
    }
}

// K5s: scale + softmax of the gram matrix -> g_attn
__global__ __launch_bounds__(256) void k5s_softmax(const float* __restrict__ temp_sc) {
    int bh = blockIdx.x;
    int h = bh & 7;
    __shared__ float att[32][33];
    __shared__ float ivqs[32], ivks[32];
    int tid = threadIdx.x;
    if (tid < 32) ivqs[tid] = inv_norm(g_sumsq[2048 + bh * 32 + tid]);
    else if (tid < 64) ivks[tid - 32] = inv_norm(g_sumsq[4096 + bh * 32 + tid - 32]);
    __syncthreads();
    float temp = temp_sc[h];
#pragma unroll
    for (int i = 0; i < 4; i++) {
        int idx = tid + i * 256;
        int r = idx >> 5, c = idx & 31;
        att[r][c] = g_gram[bh * 1024 + idx] * ivqs[r] * ivks[c] * temp;
    }
    __syncthreads();
    int w = tid >> 5, l = tid & 31;
#pragma unroll
    for (int r0 = 0; r0 < 4; r0++) {
        int r = w * 4 + r0;
        float v = att[r][l];
        float m = v;
#pragma unroll
        for (int o = 16; o > 0; o >>= 1) m = fmaxf(m, __shfl_xor_sync(0xffffffffu, m, o));
        float e = fexp(v - m);
        float sum = e;
#pragma unroll
        for (int o = 16; o > 0; o >>= 1) sum += __shfl_xor_sync(0xffffffffu, sum, o);
        g_attn[bh * 1024 + r * 32 + l] = e / sum;
    }
}

// ---------------------------------------------------------------------------
// K6: combine
// ---------------------------------------------------------------------------
__global__ __launch_bounds__(128) void k6_combine(float* __restrict__ out) {
    int ch = blockIdx.x;
    int bh = blockIdx.y;
    int b = bh >> 3, h = bh & 7;
    __shared__ float vcs[32][128];
    __shared__ float sas[128][33];
    __shared__ float att[1024];
    int tid = threadIdx.x;

    const __half* vsrc = g_proj + ((size_t)5 * 2048 + bh * 32) * N_ + ch * 128;
#pragma unroll
    for (int i = 0; i < 32; i++) {
        int f = tid + i * 128;
        int e = f >> 7, j = f & 127;
        vcs[e][j] = __half2float(vsrc[(size_t)e * N_ + j]);
    }
#pragma unroll
    for (int i = 0; i < 32; i++) {
        int f = tid + i * 128;
        int tp = f >> 5, dc = f & 31;
        sas[tp][dc] = __half2float(g_xsa[((size_t)(b * 8 + (tp >> 4)) * 32 + ch) * N_ +
                                         (tp & 15) * 256 + h * 32 + dc]);
    }
#pragma unroll
    for (int i = 0; i < 8; i++) att[tid + i * 128] = g_attn[bh * 1024 + tid + i * 128];
    __syncthreads();

    float acc[32];
#pragma unroll
    for (int dc = 0; dc < 32; dc++) acc[dc] = 0.f;
#pragma unroll 4
    for (int e = 0; e < 32; e++) {
        float v = vcs[e][tid];
#pragma unroll
        for (int dc = 0; dc < 32; dc++) acc[dc] += att[dc * 32 + e] * v;
    }
    float* ob = out + (size_t)(b * 256 + h * 32) * N_ + ch * 128 + tid;
#pragma unroll
    for (int dc = 0; dc < 32; dc++) ob[(size_t)dc * N_] = acc[dc] + sas[tid][dc];
}

// ---------------------------------------------------------------------------
extern "C" void kernel_launch(void* const* d_in, const int* in_sizes, int n_in,
                              void* d_out, int out_size) {
    const float* x    = (const float*)d_in[0];
    const float* Wsa  = (const float*)d_in[1];
    const float* EF   = (const float*)d_in[2];
    const float* t2sa = (const float*)d_in[3];
    const float* Wsc  = (const float*)d_in[4];
    const float* tsc  = (const float*)d_in[5];
    float* out = (float*)d_out;

    const int k1_smem = 3 * 2 * K1_TILE_HALVES * (int)sizeof(__half);  // 61440
    cudaFuncSetAttribute(k1_mma, cudaFuncAttributeMaxDynamicSharedMemorySize, k1_smem);

    k0w_pack<<<1536, 256>>>(Wsa, Wsc);
    k0x_pack<<<dim3(32, 8), 128>>>(x);
    k0e_pack<<<64, 256>>>(EF);
    k1_mma<<<dim3(32, 12, 8), 256, k1_smem>>>();
    k3_mma<<<dim3(32, 8), 256>>>();
    k3r_reduce<<<1024, 256>>>();
    k4_mma<<<dim3(32, 64), 128>>>(t2sa);
    k5_mma<<<dim3(64, 4), 256>>>();
    k5s_softmax<<<64, 256>>>(tsc);
    k6_combine<<<dim3(32, 64), 128>>>(out);
}

// round 17
// speedup vs baseline: 1.2272x; 1.0512x over previous
#include <cuda_runtime.h>
#include <cuda_bf16.h>
#include <cuda_fp16.h>
#include <math.h>
#include <stdint.h>

// Problem constants
#define B_ 8
#define C_ 256
#define N_ 4096
#define H_ 8
#define D_ 32
#define P_ 64

// Scratch (device globals; allocation-free contract)
// g_proj layout: [slab][b][row256][n] (fp16), slab: 0=q_sa,1=k_sa,2=v_sa,3=q_c,4=k_c,5=v_c
__device__ __half g_proj[6u * 8u * 256u * 4096u];     // 100 MB
__device__ float g_sumsq[3 * 2048];                   // row sum-of-squares (atomic)
__device__ float g_kvp[8][2 * 64 * 32 * 64];          // K-split partials [sp][row*64+p]
__device__ float g_kv[2 * 64 * 32 * 64];
__device__ float g_gram[64 * 32 * 32];                // channel gram partial sums (atomic)
__device__ float g_attn[64 * 32 * 32];
__device__ __half g_xsa[8u * 8u * 32u * 4096u];       // spatial out [b][h][d][n], fp16

// fp16 operands for the tensor-core GEMMs
__device__ __half g_Wh[1536 * 256];
__device__ __half g_xh[8u * 4096u * 256u];            // [b][n][c]  (transposed)
__device__ __half g_EFh[64 * 4096];                   // EF transposed: [p][n]

// ---------------------------------------------------------------------------
// helpers
// ---------------------------------------------------------------------------
__device__ __forceinline__ uint32_t smem_u32(const void* p) {
    uint32_t a;
    asm("{ .reg .u64 t; cvta.to.shared.u64 t, %1; cvt.u32.u64 %0, t; }" : "=r"(a) : "l"(p));
    return a;
}
#define CP_ASYNC16(dst, src) \
    asm volatile("cp.async.cg.shared.global [%0], [%1], 16;" :: "r"(dst), "l"(src))
#define CP_COMMIT() asm volatile("cp.async.commit_group;" ::: "memory")
#define CP_WAITG1() asm volatile("cp.async.wait_group 1;" ::: "memory")

__device__ __forceinline__ void mma_f16(float* d, const uint32_t* a, const uint32_t* bb) {
    asm volatile(
        "mma.sync.aligned.m16n8k16.row.col.f32.f16.f16.f32 "
        "{%0,%1,%2,%3}, {%4,%5,%6,%7}, {%8,%9}, {%0,%1,%2,%3};"
        : "+f"(d[0]), "+f"(d[1]), "+f"(d[2]), "+f"(d[3])
        : "r"(a[0]), "r"(a[1]), "r"(a[2]), "r"(a[3]), "r"(bb[0]), "r"(bb[1]));
}
__device__ __forceinline__ void ldsm_x4(uint32_t& r0, uint32_t& r1, uint32_t& r2,
                                        uint32_t& r3, uint32_t addr) {
    asm volatile("ldmatrix.sync.aligned.m8n8.x4.shared.b16 {%0,%1,%2,%3}, [%4];"
                 : "=r"(r0), "=r"(r1), "=r"(r2), "=r"(r3) : "r"(addr));
}
__device__ __forceinline__ void ldsm_x4t(uint32_t& r0, uint32_t& r1, uint32_t& r2,
                                         uint32_t& r3, uint32_t addr) {
    asm volatile("ldmatrix.sync.aligned.m8n8.x4.trans.shared.b16 {%0,%1,%2,%3}, [%4];"
                 : "=r"(r0), "=r"(r1), "=r"(r2), "=r"(r3) : "r"(addr));
}

// FFMA-only exp (avoids MUFU pipe), ~2e-6 relative accuracy.
__device__ __forceinline__ float fexp(float x) {
    const float L2E = 1.4426950408889634f;
    float t = fmaf(x, L2E, 12582912.0f);
    float n = t - 12582912.0f;
    float f = fmaf(x, L2E, -n);
    float p = 1.33978035e-3f;
    p = fmaf(p, f, 9.67770915e-3f);
    p = fmaf(p, f, 5.55041086e-2f);
    p = fmaf(p, f, 2.40226507e-1f);
    p = fmaf(p, f, 6.93147182e-1f);
    p = fmaf(p, f, 1.0f);
    int e = __float2int_rn(n);
    if (e < -126) e = -126;
    if (e > 126) e = 126;
    return __int_as_float((e + 127) << 23) * p;
}

__device__ __forceinline__ float inv_norm(float ss) {
    return 1.f / fmaxf(sqrtf(ss), 1e-12f);
}

// ---------------------------------------------------------------------------
// K0w: pack weights into fp16 (GEMM row order) + zero accumulators.
// ---------------------------------------------------------------------------
__global__ __launch_bounds__(256) void k0w_pack(const float* __restrict__ Wsa,
                                                const float* __restrict__ Wsc) {
    int e = blockIdx.x * 256 + threadIdx.x;       // 0 .. 393215
    if (e < 3 * 2048) g_sumsq[e] = 0.f;
    if (e < 64 * 32 * 32) g_gram[e] = 0.f;
    int r = e >> 8, c = e & 255;
    int p = (r >= 768) ? 1 : 0;
    int rr = r - p * 768;
    int t = rr >> 8;
    const float* Wp = p ? Wsc : Wsa;
    int srow = rr + ((p == 0 && t == 2) ? 256 : 0);
    g_Wh[e] = __float2half(Wp[(size_t)srow * 256 + c]);
}

// ---------------------------------------------------------------------------
// K0x: transpose x [b][c][n] -> [b][n][c], fp16.
// ---------------------------------------------------------------------------
__global__ __launch_bounds__(128) void k0x_pack(const float* __restrict__ x) {
    int n0 = blockIdx.x * 128;
    int b = blockIdx.y;
    __shared__ float sm[64][132];
    int tid = threadIdx.x;
    const float* xb = x + (size_t)b * C_ * N_;

    for (int c0 = 0; c0 < 256; c0 += 64) {
#pragma unroll
        for (int i = 0; i < 16; i++) {
            int u = tid + i * 128;
            int c = u >> 5, nq = u & 31;
            *(float4*)&sm[c][nq * 4] =
                *(const float4*)(xb + (size_t)(c0 + c) * N_ + n0 + nq * 4);
        }
        __syncthreads();
        uint32_t buf[32];
#pragma unroll
        for (int c = 0; c < 64; c += 2) {
            __half2 hv = __floats2half2_rn(sm[c][tid], sm[c + 1][tid]);
            buf[c >> 1] = *(uint32_t*)&hv;
        }
        size_t obase = ((size_t)b * 4096 + n0 + tid) * 256 + c0;
#pragma unroll
        for (int j = 0; j < 8; j++)
            *(uint4*)&g_xh[obase + j * 8] = *(uint4*)&buf[j * 4];
        __syncthreads();
    }
}

// ---------------------------------------------------------------------------
// K0e: transpose EF [n][p] fp32 -> g_EFh [p][n] fp16.
// ---------------------------------------------------------------------------
__global__ __launch_bounds__(256) void k0e_pack(const float* __restrict__ EF) {
    __shared__ float tile[64][65];
    int n0 = blockIdx.x * 64;
    int tid = threadIdx.x;
#pragma unroll
    for (int i = 0; i < 16; i++) {
        int u = tid + i * 256;
        int r = u >> 6, c = u & 63;
        tile[c][r] = EF[(size_t)(n0 + r) * 64 + c];
    }
    __syncthreads();
#pragma unroll
    for (int i = 0; i < 16; i++) {
        int u = tid + i * 256;
        int p = u >> 6, j = u & 63;
        g_EFh[(size_t)p * 4096 + n0 + j] = __float2half(tile[p][j]);
    }
}

// ---------------------------------------------------------------------------
// K1: fp16 mma.sync GEMM; 3-stage pipeline; both-h fragment preload
// (all 12 LDSM issued before any MMA -> h1 LDSM latency hides under h0 MMAs).
// CTA 128m x 128n; 8 warps (2m x 4n); 8 k32 steps.
// ---------------------------------------------------------------------------
#define K1_TSTRIDE 40
#define K1_TILE_HALVES (128 * K1_TSTRIDE)

__global__ __launch_bounds__(256, 2) void k1_mma() {
    extern __shared__ __half sm1[];
    const int n0 = blockIdx.x * 128;
    const int my = blockIdx.y;                  // 0..11
    const int b  = blockIdx.z;
    const int m0 = my * 128;

    const int tid = threadIdx.x;
    const int wid = tid >> 5, lane = tid & 31;
    const int wm = (wid & 1) * 64, wn = (wid >> 1) * 32;
    const int g = lane >> 2, t4 = lane & 3;

    const int x4_row = lane & 15, x4_col = (lane >> 4) * 8;

#define TILE(buf, t) (sm1 + ((buf) * 2 + (t)) * K1_TILE_HALVES)

    float acc[4][4][4];
#pragma unroll
    for (int mt = 0; mt < 4; mt++)
#pragma unroll
        for (int nt = 0; nt < 4; nt++)
#pragma unroll
            for (int j = 0; j < 4; j++) acc[mt][nt][j] = 0.f;

    const int lr0 = tid >> 2;
    const int ls0 = (tid & 3) * 8;

#define LOAD_STEP(kc, buf)                                                              \
    do {                                                                                \
        int _k0 = (kc) * 32;                                                            \
        const __half* _A = g_Wh + (size_t)m0 * 256 + _k0;                               \
        const __half* _B = g_xh + ((size_t)b * 4096 + n0) * 256 + _k0;                  \
        CP_ASYNC16(smem_u32(TILE(buf,0) + lr0 * K1_TSTRIDE + ls0), _A + (size_t)lr0 * 256 + ls0); \
        CP_ASYNC16(smem_u32(TILE(buf,0) + (lr0+64) * K1_TSTRIDE + ls0), _A + (size_t)(lr0+64) * 256 + ls0); \
        CP_ASYNC16(smem_u32(TILE(buf,1) + lr0 * K1_TSTRIDE + ls0), _B + (size_t)lr0 * 256 + ls0); \
        CP_ASYNC16(smem_u32(TILE(buf,1) + (lr0+64) * K1_TSTRIDE + ls0), _B + (size_t)(lr0+64) * 256 + ls0); \
    } while (0)

    LOAD_STEP(0, 0); CP_COMMIT();
    LOAD_STEP(1, 1); CP_COMMIT();

    for (int s = 0; s < 8; s++) {
        const int buf = s % 3;
        CP_WAITG1();
        __syncthreads();

        if (s + 2 < 8) LOAD_STEP(s + 2, (s + 2) % 3);
        CP_COMMIT();

        uint32_t af[2][4][4], bfr[2][4][2];
#pragma unroll
        for (int h = 0; h < 2; h++) {
            const __half* Abase = TILE(buf, 0) + (size_t)x4_row * K1_TSTRIDE + h * 16 + x4_col;
            const __half* Bbase = TILE(buf, 1) + (size_t)x4_row * K1_TSTRIDE + h * 16 + x4_col;
#pragma unroll
            for (int mt = 0; mt < 4; mt++)
                ldsm_x4(af[h][mt][0], af[h][mt][1], af[h][mt][2], af[h][mt][3],
                        smem_u32(Abase + (wm + mt * 16) * K1_TSTRIDE));
#pragma unroll
            for (int pr = 0; pr < 2; pr++)
                ldsm_x4(bfr[h][2 * pr][0], bfr[h][2 * pr + 1][0],
                        bfr[h][2 * pr][1], bfr[h][2 * pr + 1][1],
                        smem_u32(Bbase + (wn + pr * 16) * K1_TSTRIDE));
        }
#pragma unroll
        for (int h = 0; h < 2; h++)
#pragma unroll
            for (int mt = 0; mt < 4; mt++)
#pragma unroll
                for (int nt = 0; nt < 4; nt++)
                    mma_f16(acc[mt][nt], af[h][mt], bfr[h][nt]);
    }
#undef LOAD_STEP
#undef TILE

    // epilogue -> g_proj (fp16) + fused sumsq for slabs 0,3,4
    const int slab = my >> 1;
    const int rb = (my & 1) * 128;
    const int which = (slab == 0) ? 0 : (slab == 3 ? 1 : (slab == 4 ? 2 : -1));
#pragma unroll
    for (int mt = 0; mt < 4; mt++) {
        int r0 = rb + wm + mt * 16 + g;
        __half* p0 = g_proj + (((size_t)slab * 8 + b) * 256 + r0) * (size_t)N_ + n0 + wn;
        __half* p1 = p0 + 8 * (size_t)N_;
        float ss0 = 0.f, ss1 = 0.f;
#pragma unroll
        for (int nt = 0; nt < 4; nt++) {
            float a0 = acc[mt][nt][0], a1 = acc[mt][nt][1];
            float a2 = acc[mt][nt][2], a3 = acc[mt][nt][3];
            *(__half2*)(p0 + nt * 8 + 2 * t4) = __floats2half2_rn(a0, a1);
            *(__half2*)(p1 + nt * 8 + 2 * t4) = __floats2half2_rn(a2, a3);
            ss0 += a0 * a0 + a1 * a1;
            ss1 += a2 * a2 + a3 * a3;
        }
        if (which >= 0) {
            ss0 += __shfl_xor_sync(0xffffffffu, ss0, 1);
            ss0 += __shfl_xor_sync(0xffffffffu, ss0, 2);
            ss1 += __shfl_xor_sync(0xffffffffu, ss1, 1);
            ss1 += __shfl_xor_sync(0xffffffffu, ss1, 2);
            if (t4 == 0) {
                int row = b * 256 + r0;
                atomicAdd(&g_sumsq[which * 2048 + row], ss0);
                atomicAdd(&g_sumsq[which * 2048 + row + 8], ss1);
            }
        }
    }
}

// ---------------------------------------------------------------------------
// K3: Linformer projection GEMM; 3-stage pipeline; both-h fragment preload.
// CTA 128m x 64n; 8 warps (4m x 2n); 16 k32 steps; K-split 8.
// ---------------------------------------------------------------------------
#define K3_STRIDE 40
__global__ __launch_bounds__(256) void k3_mma() {
    __shared__ __half As[3][128][K3_STRIDE];
    __shared__ __half Bs[3][64][K3_STRIDE];
    const int m0 = blockIdx.x * 128;
    const int sp = blockIdx.y;
    const int kb = sp * 512;

    const int tid = threadIdx.x;
    const int wid = tid >> 5, lane = tid & 31;
    const int wm = (wid >> 1) * 32;
    const int wn = (wid & 1) * 32;
    const int g = lane >> 2, t4 = lane & 3;

    const int x4_row = lane & 15, x4_col = (lane >> 4) * 8;

    const __half* Ag = g_proj + (size_t)2048 * N_;

    float acc[2][4][4];
#pragma unroll
    for (int mt = 0; mt < 2; mt++)
#pragma unroll
        for (int nt = 0; nt < 4; nt++)
#pragma unroll
            for (int j = 0; j < 4; j++) acc[mt][nt][j] = 0.f;

    const int lr = tid >> 2;
    const int ls = (tid & 3) * 8;

#define K3_LOAD(kc, buf)                                                                \
    do {                                                                                \
        int _k0 = kb + (kc) * 32;                                                       \
        const __half* _A = Ag + (size_t)m0 * 4096 + _k0;                                \
        const __half* _B = g_EFh + _k0;                                                 \
        CP_ASYNC16(smem_u32(&As[buf][lr][ls]), _A + (size_t)lr * 4096 + ls);            \
        CP_ASYNC16(smem_u32(&As[buf][lr + 64][ls]), _A + (size_t)(lr + 64) * 4096 + ls);\
        CP_ASYNC16(smem_u32(&Bs[buf][lr][ls]), _B + (size_t)lr * 4096 + ls);            \
    } while (0)

    K3_LOAD(0, 0); CP_COMMIT();
    K3_LOAD(1, 1); CP_COMMIT();

    for (int s = 0; s < 16; s++) {
        const int buf = s % 3;
        CP_WAITG1();
        __syncthreads();

        if (s + 2 < 16) K3_LOAD(s + 2, (s + 2) % 3);
        CP_COMMIT();

        uint32_t af[2][2][4], bfr[2][4][2];
#pragma unroll
        for (int h = 0; h < 2; h++) {
            const __half* Abase = &As[buf][x4_row][h * 16 + x4_col];
            const __half* Bbase = &Bs[buf][x4_row][h * 16 + x4_col];
#pragma unroll
            for (int mt = 0; mt < 2; mt++)
                ldsm_x4(af[h][mt][0], af[h][mt][1], af[h][mt][2], af[h][mt][3],
                        smem_u32(Abase + (wm + mt * 16) * K3_STRIDE));
#pragma unroll
            for (int pr = 0; pr < 2; pr++)
                ldsm_x4(bfr[h][2 * pr][0], bfr[h][2 * pr + 1][0],
                        bfr[h][2 * pr][1], bfr[h][2 * pr + 1][1],
                        smem_u32(Bbase + (wn + pr * 16) * K3_STRIDE));
        }
#pragma unroll
        for (int h = 0; h < 2; h++)
#pragma unroll
            for (int mt = 0; mt < 2; mt++)
#pragma unroll
                for (int nt = 0; nt < 4; nt++)
                    mma_f16(acc[mt][nt], af[h][mt], bfr[h][nt]);
    }
#undef K3_LOAD

#pragma unroll
    for (int mt = 0; mt < 2; mt++) {
        int row = m0 + wm + mt * 16 + g;
        float* p0 = &g_kvp[sp][(size_t)row * 64 + wn];
        float* p1 = p0 + 8 * 64;
#pragma unroll
        for (int nt = 0; nt < 4; nt++) {
            *(float2*)(p0 + nt * 8 + 2 * t4) = make_float2(acc[mt][nt][0], acc[mt][nt][1]);
            *(float2*)(p1 + nt * 8 + 2 * t4) = make_float2(acc[mt][nt][2], acc[mt][nt][3]);
        }
    }
}

__global__ __launch_bounds__(256) void k3r_reduce() {
    int i = blockIdx.x * 256 + threadIdx.x;
    float s = 0.f;
#pragma unroll
    for (int sp = 0; sp < 8; sp++) s += g_kvp[sp][i];
    g_kv[i] = s;
}

// ---------------------------------------------------------------------------
// K4: spatial attention on tensor cores (flash-style, fused softmax).
// ---------------------------------------------------------------------------
__global__ __launch_bounds__(128) void k4_mma(const float* __restrict__ temp2_sa) {
    __shared__ __align__(16) __half sQ[32][136];   // [d][n]
    __shared__ __align__(16) __half sK[64][40];    // [p][d], pre-scaled
    __shared__ __align__(16) __half sV[32][72];    // [d][p]
    __shared__ __align__(16) __half sO[32][136];   // [d][n]
    __shared__ float ivs[32];
    const int tid = threadIdx.x;
    const int lane = tid & 31, w = tid >> 5;
    const int n0 = blockIdx.x * 128;
    const int bh = blockIdx.y;
    const int h = bh & 7;
    const int g = lane >> 2, t4 = lane & 3;

    if (tid < 32) ivs[tid] = inv_norm(g_sumsq[bh * 32 + tid]);
    __syncthreads();
    const float temp = temp2_sa[h];

#pragma unroll
    for (int i = 0; i < 16; i++) {
        int u = tid + i * 128;
        int d = u >> 6, p = u & 63;
        sK[p][d] = __float2half(g_kv[bh * 2048 + d * 64 + p] * ivs[d] * temp);
        sV[d][p] = __float2half(g_kv[(64 + bh) * 2048 + d * 64 + p]);
    }
    const __half* qb = g_proj + (size_t)(bh * 32) * N_ + n0;
#pragma unroll
    for (int i = 0; i < 4; i++) {
        int u = tid + i * 128;
        int d = u >> 4, sg = u & 15;
        *(uint4*)&sQ[d][sg * 8] = *(const uint4*)(qb + (size_t)d * N_ + sg * 8);
    }
    __syncthreads();

    // ---- GEMM1: S = Q^T x Ksc  (M=32 rows/warp, N=64, K=32) ----
    const int a_d = (lane & 7) | (((lane >> 4) & 1) << 3);
    const int a_noff = ((lane >> 3) & 1) * 8;
    const int x4_row = lane & 15, x4_col = (lane >> 4) * 8;

    float acc[2][8][4];
#pragma unroll
    for (int mt = 0; mt < 2; mt++)
#pragma unroll
        for (int nt = 0; nt < 8; nt++)
#pragma unroll
            for (int j = 0; j < 4; j++) acc[mt][nt][j] = 0.f;

#pragma unroll
    for (int h2 = 0; h2 < 2; h2++) {
        uint32_t af[2][4], bfr[8][2];
#pragma unroll
        for (int mt = 0; mt < 2; mt++)
            ldsm_x4t(af[mt][0], af[mt][1], af[mt][2], af[mt][3],
                     smem_u32(&sQ[a_d + h2 * 16][w * 32 + mt * 16 + a_noff]));
#pragma unroll
        for (int pr = 0; pr < 4; pr++)
            ldsm_x4(bfr[2 * pr][0], bfr[2 * pr + 1][0],
                    bfr[2 * pr][1], bfr[2 * pr + 1][1],
                    smem_u32(&sK[pr * 16 + x4_row][x4_col + h2 * 16]));
#pragma unroll
        for (int mt = 0; mt < 2; mt++)
#pragma unroll
            for (int nt = 0; nt < 8; nt++)
                mma_f16(acc[mt][nt], af[mt], bfr[nt]);
    }

    // ---- softmax over p (64), rows spread over t4 quad ----
    float isr[2][2];
    uint32_t pa[2][4][4];
#pragma unroll
    for (int mt = 0; mt < 2; mt++) {
        float m0 = -1e30f, m1 = -1e30f;
#pragma unroll
        for (int nt = 0; nt < 8; nt++) {
            m0 = fmaxf(m0, fmaxf(acc[mt][nt][0], acc[mt][nt][1]));
            m1 = fmaxf(m1, fmaxf(acc[mt][nt][2], acc[mt][nt][3]));
        }
        m0 = fmaxf(m0, __shfl_xor_sync(0xffffffffu, m0, 1));
        m0 = fmaxf(m0, __shfl_xor_sync(0xffffffffu, m0, 2));
        m1 = fmaxf(m1, __shfl_xor_sync(0xffffffffu, m1, 1));
        m1 = fmaxf(m1, __shfl_xor_sync(0xffffffffu, m1, 2));
        float s0 = 0.f, s1 = 0.f;
#pragma unroll
        for (int nt = 0; nt < 8; nt++) {
            acc[mt][nt][0] = fexp(acc[mt][nt][0] - m0);
            acc[mt][nt][1] = fexp(acc[mt][nt][1] - m0);
            acc[mt][nt][2] = fexp(acc[mt][nt][2] - m1);
            acc[mt][nt][3] = fexp(acc[mt][nt][3] - m1);
            s0 += acc[mt][nt][0] + acc[mt][nt][1];
            s1 += acc[mt][nt][2] + acc[mt][nt][3];
        }
        s0 += __shfl_xor_sync(0xffffffffu, s0, 1);
        s0 += __shfl_xor_sync(0xffffffffu, s0, 2);
        s1 += __shfl_xor_sync(0xffffffffu, s1, 1);
        s1 += __shfl_xor_sync(0xffffffffu, s1, 2);
        isr[mt][0] = 1.f / s0;
        isr[mt][1] = 1.f / s1;
#pragma unroll
        for (int kk = 0; kk < 4; kk++) {
            __half2 h0 = __floats2half2_rn(acc[mt][2 * kk][0], acc[mt][2 * kk][1]);
            __half2 h1 = __floats2half2_rn(acc[mt][2 * kk][2], acc[mt][2 * kk][3]);
            __half2 h2a = __floats2half2_rn(acc[mt][2 * kk + 1][0], acc[mt][2 * kk + 1][1]);
            __half2 h3 = __floats2half2_rn(acc[mt][2 * kk + 1][2], acc[mt][2 * kk + 1][3]);
            pa[mt][kk][0] = *(uint32_t*)&h0;
            pa[mt][kk][1] = *(uint32_t*)&h1;
            pa[mt][kk][2] = *(uint32_t*)&h2a;
            pa[mt][kk][3] = *(uint32_t*)&h3;
        }
    }

    // ---- GEMM2: O = P x V^T  (M=32/warp, N=32 d, K=64 p) ----
    float o[2][4][4];
#pragma unroll
    for (int mt = 0; mt < 2; mt++)
#pragma unroll
        for (int nt = 0; nt < 4; nt++)
#pragma unroll
            for (int j = 0; j < 4; j++) o[mt][nt][j] = 0.f;

#pragma unroll
    for (int kk = 0; kk < 4; kk++) {
        uint32_t bfr[4][2];
#pragma unroll
        for (int pr = 0; pr < 2; pr++)
            ldsm_x4(bfr[2 * pr][0], bfr[2 * pr + 1][0],
                    bfr[2 * pr][1], bfr[2 * pr + 1][1],
                    smem_u32(&sV[pr * 16 + x4_row][x4_col + kk * 16]));
#pragma unroll
        for (int mt = 0; mt < 2; mt++)
#pragma unroll
            for (int nt = 0; nt < 4; nt++)
                mma_f16(o[mt][nt], pa[mt][kk], bfr[nt]);
    }

    // ---- scale by 1/sum, stage to sO [d][n], write out coalesced ----
#pragma unroll
    for (int mt = 0; mt < 2; mt++) {
        int r0 = w * 32 + mt * 16 + g;
#pragma unroll
        for (int nt = 0; nt < 4; nt++) {
            int d0 = nt * 8 + 2 * t4;
            sO[d0][r0]         = __float2half(o[mt][nt][0] * isr[mt][0]);
            sO[d0 + 1][r0]     = __float2half(o[mt][nt][1] * isr[mt][0]);
            sO[d0][r0 + 8]     = __float2half(o[mt][nt][2] * isr[mt][1]);
            sO[d0 + 1][r0 + 8] = __float2half(o[mt][nt][3] * isr[mt][1]);
        }
    }
    __syncthreads();
    __half* ob = g_xsa + (size_t)(bh * 32) * N_ + n0;
#pragma unroll
    for (int i = 0; i < 4; i++) {
        int u = tid + i * 128;
        int d = u >> 4, sg = u & 15;
        *(uint4*)(ob + (size_t)d * N_ + sg * 8) = *(uint4*)&sO[d][sg * 8];
    }
}

// ---------------------------------------------------------------------------
// K5: channel gram on tensor cores. Grid (bh, 4 n-splits), 256 threads.
// ---------------------------------------------------------------------------
__global__ __launch_bounds__(256) void k5_mma() {
    int bh = blockIdx.x;
    int sp = blockIdx.y;
    __shared__ __align__(16) __half qcs[32][136], kcs[32][136];
    __shared__ float red[8][32][33];
    int tid = threadIdx.x;
    int w = tid >> 5, lane = tid & 31;
    const int x4_row = lane & 15, x4_col = (lane >> 4) * 8;
    const int g = lane >> 2, t4 = lane & 3;
    const __half* qsrc = g_proj + ((size_t)3 * 2048 + bh * 32) * N_;
    const __half* ksrc = g_proj + ((size_t)4 * 2048 + bh * 32) * N_;

    float acc[2][4][4];
#pragma unroll
    for (int mt = 0; mt < 2; mt++)
#pragma unroll
        for (int nt = 0; nt < 4; nt++)
#pragma unroll
            for (int j = 0; j < 4; j++) acc[mt][nt][j] = 0.f;

    for (int cc = 0; cc < 8; cc++) {
        int c0 = sp * 1024 + cc * 128;
#pragma unroll
        for (int i = 0; i < 2; i++) {
            int u = tid + i * 256;
            int r = u >> 4, sg = u & 15;
            *(uint4*)&qcs[r][sg * 8] = *(const uint4*)(qsrc + (size_t)r * N_ + c0 + sg * 8);
            *(uint4*)&kcs[r][sg * 8] = *(const uint4*)(ksrc + (size_t)r * N_ + c0 + sg * 8);
        }
        __syncthreads();
        uint32_t af[2][4], bfr[4][2];
#pragma unroll
        for (int mt = 0; mt < 2; mt++)
            ldsm_x4(af[mt][0], af[mt][1], af[mt][2], af[mt][3],
                    smem_u32(&qcs[mt * 16 + x4_row][w * 16 + x4_col]));
#pragma unroll
        for (int pr = 0; pr < 2; pr++)
            ldsm_x4(bfr[2 * pr][0], bfr[2 * pr + 1][0],
                    bfr[2 * pr][1], bfr[2 * pr + 1][1],
                    smem_u32(&kcs[pr * 16 + x4_row][w * 16 + x4_col]));
#pragma unroll
        for (int mt = 0; mt < 2; mt++)
#pragma unroll
            for (int nt = 0; nt < 4; nt++)
                mma_f16(acc[mt][nt], af[mt], bfr[nt]);
        __syncthreads();
    }

#pragma unroll
    for (int mt = 0; mt < 2; mt++) {
        int r = mt * 16 + g;
#pragma unroll
        for (int nt = 0; nt < 4; nt++) {
            int c = nt * 8 + 2 * t4;
            red[w][r][c]         = acc[mt][nt][0];
            red[w][r][c + 1]     = acc[mt][nt][1];
            red[w][r + 8][c]     = acc[mt][nt][2];
            red[w][r + 8][c + 1] = acc[mt][nt][3];
        }
    }
    __syncthreads();
#pragma unroll
    for (int i = 0; i < 4; i++) {
        int idx = tid + i * 256;
        int r = idx >> 5, c = idx & 31;
        float s = 0.f;
#pragma unroll
        for (int ww = 0; ww < 8; ww++) s += red[ww][r][c];
        atomicAdd(&g_gram[bh * 1024 + idx], s);
    }
}

// K5s: scale + softmax of the gram matrix -> g_attn
__global__ __launch_bounds__(256) void k5s_softmax(const float* __restrict__ temp_sc) {
    int bh = blockIdx.x;
    int h = bh & 7;
    __shared__ float att[32][33];
    __shared__ float ivqs[32], ivks[32];
    int tid = threadIdx.x;
    if (tid < 32) ivqs[tid] = inv_norm(g_sumsq[2048 + bh * 32 + tid]);
    else if (tid < 64) ivks[tid - 32] = inv_norm(g_sumsq[4096 + bh * 32 + tid - 32]);
    __syncthreads();
    float temp = temp_sc[h];
#pragma unroll
    for (int i = 0; i < 4; i++) {
        int idx = tid + i * 256;
        int r = idx >> 5, c = idx & 31;
        att[r][c] = g_gram[bh * 1024 + idx] * ivqs[r] * ivks[c] * temp;
    }
    __syncthreads();
    int w = tid >> 5, l = tid & 31;
#pragma unroll
    for (int r0 = 0; r0 < 4; r0++) {
        int r = w * 4 + r0;
        float v = att[r][l];
        float m = v;
#pragma unroll
        for (int o = 16; o > 0; o >>= 1) m = fmaxf(m, __shfl_xor_sync(0xffffffffu, m, o));
        float e = fexp(v - m);
        float sum = e;
#pragma unroll
        for (int o = 16; o > 0; o >>= 1) sum += __shfl_xor_sync(0xffffffffu, sum, o);
        g_attn[bh * 1024 + r * 32 + l] = e / sum;
    }
}

// ---------------------------------------------------------------------------
// K6: combine
// ---------------------------------------------------------------------------
__global__ __launch_bounds__(128) void k6_combine(float* __restrict__ out) {
    int ch = blockIdx.x;
    int bh = blockIdx.y;
    int b = bh >> 3, h = bh & 7;
    __shared__ float vcs[32][128];
    __shared__ float sas[128][33];
    __shared__ float att[1024];
    int tid = threadIdx.x;

    const __half* vsrc = g_proj + ((size_t)5 * 2048 + bh * 32) * N_ + ch * 128;
#pragma unroll
    for (int i = 0; i < 32; i++) {
        int f = tid + i * 128;
        int e = f >> 7, j = f & 127;
        vcs[e][j] = __half2float(vsrc[(size_t)e * N_ + j]);
    }
#pragma unroll
    for (int i = 0; i < 32; i++) {
        int f = tid + i * 128;
        int tp = f >> 5, dc = f & 31;
        sas[tp][dc] = __half2float(g_xsa[((size_t)(b * 8 + (tp >> 4)) * 32 + ch) * N_ +
                                         (tp & 15) * 256 + h * 32 + dc]);
    }
#pragma unroll
    for (int i = 0; i < 8; i++) att[tid + i * 128] = g_attn[bh * 1024 + tid + i * 128];
    __syncthreads();

    float acc[32];
#pragma unroll
    for (int dc = 0; dc < 32; dc++) acc[dc] = 0.f;
#pragma unroll 4
    for (int e = 0; e < 32; e++) {
        float v = vcs[e][tid];
#pragma unroll
        for (int dc = 0; dc < 32; dc++) acc[dc] += att[dc * 32 + e] * v;
    }
    float* ob = out + (size_t)(b * 256 + h * 32) * N_ + ch * 128 + tid;
#pragma unroll
    for (int dc = 0; dc < 32; dc++) ob[(size_t)dc * N_] = acc[dc] + sas[tid][dc];
}

// ---------------------------------------------------------------------------
extern "C" void kernel_launch(void* const* d_in, const int* in_sizes, int n_in,
                              void* d_out, int out_size) {
    const float* x    = (const float*)d_in[0];
    const float* Wsa  = (const float*)d_in[1];
    const float* EF   = (const float*)d_in[2];
    const float* t2sa = (const float*)d_in[3];
    const float* Wsc  = (const float*)d_in[4];
    const float* tsc  = (const float*)d_in[5];
    float* out = (float*)d_out;

    const int k1_smem = 3 * 2 * K1_TILE_HALVES * (int)sizeof(__half);  // 61440
    cudaFuncSetAttribute(k1_mma, cudaFuncAttributeMaxDynamicSharedMemorySize, k1_smem);

    k0w_pack<<<1536, 256>>>(Wsa, Wsc);
    k0x_pack<<<dim3(32, 8), 128>>>(x);
    k0e_pack<<<64, 256>>>(EF);
    k1_mma<<<dim3(32, 12, 8), 256, k1_smem>>>();
    k3_mma<<<dim3(32, 8), 256>>>();
    k3r_reduce<<<1024, 256>>>();
    k4_mma<<<dim3(32, 64), 128>>>(t2sa);
    k5_mma<<<dim3(64, 4), 256>>>();
    k5s_softmax<<<64, 256>>>(tsc);
    k6_combine<<<dim3(32, 64), 128>>>(out);
}